// round 3
// baseline (speedup 1.0000x reference)
#include <cuda_runtime.h>
#include <math.h>

#define NV     12
#define BATCH  4096
#define DIM    128
#define ALPHA  0.4f
#define BETA   2.0f
#define LAMDA  2.0f

#define B_PER_BLK 8            // batch elements per block
#define THREADS   128          // 16 threads per batch element
#define NBLOCKS   (BATCH / B_PER_BLK)    // 512
#define CHUNK     32           // k-dims staged per chunk
#define NCHUNK    (DIM / CHUNK)          // 4
#define PITCH     36           // floats per smem row (32 data + 4 pad)
#define ROWS      24           // 12 A rows + 12 N rows
#define BAREA     (ROWS * PITCH)         // 864 floats per batch element
#define TILEF     (B_PER_BLK * BAREA)    // 6912 floats per buffer
#define SMEM_BYTES (2 * TILEF * 4)       // 55296 B dynamic

// Per-block partials + completion ticket (device globals: zero-initialized)
__device__ float g_pl[NBLOCKS];
__device__ float g_pc[NBLOCKS];
__device__ float g_pm[NBLOCKS];
__device__ float g_pa[NBLOCKS];
__device__ float g_pmin[NBLOCKS];
__device__ unsigned int g_ticket;

__device__ __forceinline__ float dot4(float4 a, float4 b) {
    return a.x * b.x + a.y * b.y + a.z * b.z + a.w * b.w;
}
__device__ __forceinline__ float sqdiff4(float4 a, float4 b) {
    float x = a.x - b.x, y = a.y - b.y, z = a.z - b.z, w = a.w - b.w;
    return x * x + y * y + z * z + w * w;
}

__global__ __launch_bounds__(THREADS)
void pil_fused(const float* __restrict__ SV_A, const float* __restrict__ SV_N,
               const float* __restrict__ MV_A, const float* __restrict__ MV_N,
               float* __restrict__ out, int out_size)
{
    extern __shared__ float tile[];             // 2 buffers x TILEF floats
    __shared__ float nrm[B_PER_BLK * ROWS];
    __shared__ float r_loss[B_PER_BLK], r_cnt[B_PER_BLK];
    __shared__ float r_mc[B_PER_BLK], r_ac[B_PER_BLK], r_mn[B_PER_BLK];
    __shared__ float red[5][THREADS];
    __shared__ int   s_islast;

    const int tid = threadIdx.x;
    const int bl  = tid >> 4;
    const int t   = tid & 15;
    const int ti  = t >> 2;
    const int tj  = t & 3;
    const int bg0 = blockIdx.x * B_PER_BLK;

    // ---- precompute staging addresses (constant across chunks)
    const float* srcp[12];
    int soff[12];
    #pragma unroll
    for (int s = 0; s < 12; ++s) {
        int f   = tid + THREADS * s;       // 0..1535
        int sb  = f / (ROWS * 8);
        int rem = f - sb * (ROWS * 8);
        int row = rem >> 3;
        int k4  = rem & 7;
        const float* base = (row < NV)
            ? SV_A + ((size_t)row        * BATCH + (bg0 + sb)) * DIM
            : SV_N + ((size_t)(row - NV) * BATCH + (bg0 + sb)) * DIM;
        srcp[s] = base + k4 * 4;
        soff[s] = sb * BAREA + row * PITCH + k4 * 4;
    }

    float G[3][3] = {{0.f,0.f,0.f},{0.f,0.f,0.f},{0.f,0.f,0.f}};
    float nacc0 = 0.f, nacc1 = 0.f;

    // ---- prefetch chunk 0 into registers
    float4 pf[12];
    #pragma unroll
    for (int s = 0; s < 12; ++s)
        pf[s] = *reinterpret_cast<const float4*>(srcp[s]);

    for (int c = 0; c < NCHUNK; ++c) {
        float* tb = tile + (c & 1) * TILEF;
        // store prefetched chunk (safe: readers of this buffer passed the
        // previous iteration's barrier before we could get here)
        #pragma unroll
        for (int s = 0; s < 12; ++s)
            *reinterpret_cast<float4*>(&tb[soff[s]]) = pf[s];
        __syncthreads();

        // prefetch next chunk (overlaps the compute below)
        if (c < NCHUNK - 1) {
            #pragma unroll
            for (int s = 0; s < 12; ++s)
                pf[s] = *reinterpret_cast<const float4*>(srcp[s] + (c + 1) * CHUNK);
        }

        // ---- norm partials (192 rows; thread owns row tid, +tid+128 if tid<64)
        {
            int sb = tid / ROWS, row = tid - sb * ROWS;
            const float* rb = &tb[sb * BAREA + row * PITCH];
            float s0 = 0.f;
            #pragma unroll
            for (int k4 = 0; k4 < 8; ++k4) {
                float4 v = *reinterpret_cast<const float4*>(rb + k4 * 4);
                s0 += dot4(v, v);
            }
            nacc0 += s0;
            if (tid < B_PER_BLK * ROWS - THREADS) {
                int R1  = tid + THREADS;
                int sb1 = R1 / ROWS, row1 = R1 - sb1 * ROWS;
                const float* rb1 = &tb[sb1 * BAREA + row1 * PITCH];
                float s1 = 0.f;
                #pragma unroll
                for (int k4 = 0; k4 < 8; ++k4) {
                    float4 v = *reinterpret_cast<const float4*>(rb1 + k4 * 4);
                    s1 += dot4(v, v);
                }
                nacc1 += s1;
            }
        }

        // ---- 3x3 register-tiled Gram accumulation
        const float* A0 = &tb[bl * BAREA + (3 * ti)      * PITCH];
        const float* N0 = &tb[bl * BAREA + (NV + 3 * tj) * PITCH];
        #pragma unroll
        for (int k4 = 0; k4 < 8; ++k4) {
            float4 a0 = *reinterpret_cast<const float4*>(A0 + 0 * PITCH + k4 * 4);
            float4 a1 = *reinterpret_cast<const float4*>(A0 + 1 * PITCH + k4 * 4);
            float4 a2 = *reinterpret_cast<const float4*>(A0 + 2 * PITCH + k4 * 4);
            float4 n0 = *reinterpret_cast<const float4*>(N0 + 0 * PITCH + k4 * 4);
            float4 n1 = *reinterpret_cast<const float4*>(N0 + 1 * PITCH + k4 * 4);
            float4 n2 = *reinterpret_cast<const float4*>(N0 + 2 * PITCH + k4 * 4);
            G[0][0] += dot4(a0, n0); G[0][1] += dot4(a0, n1); G[0][2] += dot4(a0, n2);
            G[1][0] += dot4(a1, n0); G[1][1] += dot4(a1, n1); G[1][2] += dot4(a1, n2);
            G[2][0] += dot4(a2, n0); G[2][1] += dot4(a2, n1); G[2][2] += dot4(a2, n2);
        }
    }

    // publish norms
    nrm[tid] = nacc0;
    if (tid < B_PER_BLK * ROWS - THREADS) nrm[tid + THREADS] = nacc1;
    __syncthreads();

    // ---- d = na + nn - 2G, argmin with flat-index tie-break (first min)
    float dmin = 3.4e38f;
    int   imin = 0;
    #pragma unroll
    for (int r = 0; r < 3; ++r) {
        float na = nrm[bl * ROWS + 3 * ti + r];
        #pragma unroll
        for (int cc = 0; cc < 3; ++cc) {
            float nn = nrm[bl * ROWS + NV + 3 * tj + cc];
            float d  = na + nn - 2.f * G[r][cc];
            int   fl = (3 * ti + r) * NV + (3 * tj + cc);
            if (d < dmin || (d == dmin && fl < imin)) { dmin = d; imin = fl; }
        }
    }
    #pragma unroll
    for (int o = 1; o < 16; o <<= 1) {
        float od = __shfl_xor_sync(0xffffffffu, dmin, o);
        int   oi = __shfl_xor_sync(0xffffffffu, imin, o);
        if (od < dmin || (od == dmin && oi < imin)) { dmin = od; imin = oi; }
    }

    // ---- epilogue distances over 128 dims (8 dims/lane of the 16-group)
    const int confA = imin / NV;
    const int confN = imin - confA * NV;
    const int bg    = bg0 + bl;

    const float4* mva = reinterpret_cast<const float4*>(MV_A + (size_t)bg * DIM);
    const float4* mvn = reinterpret_cast<const float4*>(MV_N + (size_t)bg * DIM);
    const float4* fca = reinterpret_cast<const float4*>(SV_A + ((size_t)confA * BATCH + bg) * DIM);
    const float4* fcn = reinterpret_cast<const float4*>(SV_N + ((size_t)confN * BATCH + bg) * DIM);

    float smv = 0.f, sa = 0.f, sc = 0.f;
    #pragma unroll
    for (int q = 0; q < 2; ++q) {
        int k4 = t * 2 + q;
        float4 ma = mva[k4], mn_ = mvn[k4];
        float4 fa = fca[k4], fn  = fcn[k4];
        smv += sqdiff4(ma, mn_);
        sa  += sqdiff4(ma, fa);
        sc  += sqdiff4(mn_, fn);
    }
    #pragma unroll
    for (int o = 1; o < 16; o <<= 1) {
        smv += __shfl_xor_sync(0xffffffffu, smv, o);
        sa  += __shfl_xor_sync(0xffffffffu, sa,  o);
        sc  += __shfl_xor_sync(0xffffffffu, sc,  o);
    }

    if (t == 0) {
        float mc       = fmaxf(dmin, 0.f);
        float mv_inter = sqrtf(smv);
        float a_cl     = sqrtf(sa);
        float c_in     = sqrtf(sc);
        float loss = LAMDA * (fmaxf(BETA - mc, 0.f) + fmaxf(BETA - mv_inter, 0.f))
                   + fmaxf(a_cl - ALPHA, 0.f) + fmaxf(c_in - ALPHA, 0.f);
        float sqmc = sqrtf(mc);
        r_loss[bl] = loss;
        r_cnt[bl]  = (loss != 0.f) ? 1.f : 0.f;
        r_mc[bl]   = sqmc;
        r_ac[bl]   = sqrtf(a_cl) + sqrtf(c_in);
        r_mn[bl]   = sqmc;
    }
    __syncthreads();

    // ---- per-block partial (fixed order -> deterministic) + ticket
    if (tid == 0) {
        float sl = 0.f, sn = 0.f, sm = 0.f, sa2 = 0.f, mn = 3.4e38f;
        #pragma unroll
        for (int i = 0; i < B_PER_BLK; ++i) {
            sl  += r_loss[i];
            sn  += r_cnt[i];
            sm  += r_mc[i];
            sa2 += r_ac[i];
            mn   = fminf(mn, r_mn[i]);
        }
        g_pl[blockIdx.x]   = sl;
        g_pc[blockIdx.x]   = sn;
        g_pm[blockIdx.x]   = sm;
        g_pa[blockIdx.x]   = sa2;
        g_pmin[blockIdx.x] = mn;
        __threadfence();
        unsigned int prev = atomicAdd(&g_ticket, 1u);
        s_islast = (prev == NBLOCKS - 1) ? 1 : 0;
    }
    __syncthreads();

    // ---- last block performs the deterministic final reduction
    if (s_islast) {
        __threadfence();   // acquire: make all blocks' partials visible
        float al = 0.f, ac = 0.f, am = 0.f, aa = 0.f, amn = 3.4e38f;
        #pragma unroll
        for (int q = 0; q < NBLOCKS / THREADS; ++q) {   // 4, fixed order
            int i = tid + q * THREADS;
            al += g_pl[i];
            ac += g_pc[i];
            am += g_pm[i];
            aa += g_pa[i];
            amn = fminf(amn, g_pmin[i]);
        }
        red[0][tid] = al; red[1][tid] = ac; red[2][tid] = am;
        red[3][tid] = aa; red[4][tid] = amn;
        __syncthreads();
        for (int o = THREADS / 2; o > 0; o >>= 1) {
            if (tid < o) {
                red[0][tid] += red[0][tid + o];
                red[1][tid] += red[1][tid + o];
                red[2][tid] += red[2][tid + o];
                red[3][tid] += red[3][tid + o];
                red[4][tid]  = fminf(red[4][tid], red[4][tid + o]);
            }
            __syncthreads();
        }
        if (tid == 0) {
            const float inv = 1.f / (float)BATCH;
            if (out_size > 0) out[0] = red[0][0] * inv;
            if (out_size > 1) out[1] = red[1][0];
            if (out_size > 2) out[2] = red[2][0] * inv;
            if (out_size > 3) out[3] = 0.5f * red[3][0] * inv;
            if (out_size > 4) out[4] = red[4][0];
            for (int i = 5; i < out_size; ++i) out[i] = 0.f;
            g_ticket = 0;          // reset for next graph replay
        }
    }
}

extern "C" void kernel_launch(void* const* d_in, const int* in_sizes, int n_in,
                              void* d_out, int out_size)
{
    const float* SV_A = (const float*)d_in[0];
    const float* SV_N = (const float*)d_in[1];
    const float* MV_A = (const float*)d_in[2];
    const float* MV_N = (const float*)d_in[3];
    (void)in_sizes; (void)n_in;

    cudaFuncSetAttribute(pil_fused, cudaFuncAttributeMaxDynamicSharedMemorySize,
                         SMEM_BYTES);
    pil_fused<<<NBLOCKS, THREADS, SMEM_BYTES>>>(SV_A, SV_N, MV_A, MV_N,
                                                (float*)d_out, out_size);
}

// round 5
// speedup vs baseline: 1.4830x; 1.4830x over previous
#include <cuda_runtime.h>
#include <math.h>
#include <stdint.h>

#define NV     12
#define BATCH  4096
#define DIM    128
#define ALPHA  0.4f
#define BETA   2.0f
#define LAMDA  2.0f

#define B_PER_BLK 4            // batch elements per block (1 warp each)
#define THREADS   128
#define NBLOCKS   (BATCH / B_PER_BLK)    // 1024
#define CHUNK     32           // k-dims staged per chunk
#define NCHUNK    (DIM / CHUNK)          // 4
#define PITCH     36           // floats per smem row (32 data + 4 pad) = 144B
#define ROWS      24           // 12 A rows + 12 N rows
#define BAREA     (ROWS * PITCH)         // 864 floats per element
#define TILEF     (B_PER_BLK * BAREA)    // 3456 floats per buffer
#define NSTAGE    6            // float4 staged per thread per chunk

// Per-block partials + ticket (device globals, zero-initialized)
__device__ float g_pl[NBLOCKS];
__device__ float g_pc[NBLOCKS];
__device__ float g_pm[NBLOCKS];
__device__ float g_pa[NBLOCKS];
__device__ float g_pmin[NBLOCKS];
__device__ unsigned int g_ticket;

__device__ __forceinline__ float dot4(float4 a, float4 b) {
    return a.x * b.x + a.y * b.y + a.z * b.z + a.w * b.w;
}
__device__ __forceinline__ float sqdiff4(float4 a, float4 b) {
    float x = a.x - b.x, y = a.y - b.y, z = a.z - b.z, w = a.w - b.w;
    return x * x + y * y + z * z + w * w;
}
__device__ __forceinline__ void cp_async16(uint32_t saddr, const void* gptr) {
    asm volatile("cp.async.cg.shared.global [%0], [%1], 16;"
                 :: "r"(saddr), "l"(gptr));
}
#define CP_COMMIT()  asm volatile("cp.async.commit_group;")
#define CP_WAIT(N)   asm volatile("cp.async.wait_group %0;" :: "n"(N))

__global__ __launch_bounds__(THREADS)
void pil_fused(const float* __restrict__ SV_A, const float* __restrict__ SV_N,
               const float* __restrict__ MV_A, const float* __restrict__ MV_N,
               float* __restrict__ out, int out_size)
{
    __shared__ float tile[2][TILEF];            // 27.6 KB double buffer
    __shared__ float nrm[B_PER_BLK * ROWS];     // 96 row norms
    __shared__ float r_loss[B_PER_BLK], r_cnt[B_PER_BLK];
    __shared__ float r_mc[B_PER_BLK], r_ac[B_PER_BLK], r_mn[B_PER_BLK];
    __shared__ float red[5][THREADS];
    __shared__ int   s_islast;

    const int tid  = threadIdx.x;
    const int w    = tid >> 5;       // warp = local batch element 0..3
    const int lane = tid & 31;
    const int h    = lane >> 4;      // k-half: dims [h*16, h*16+16) of chunk
    const int t    = lane & 15;
    const int ti   = t >> 2;         // A rows 3*ti..3*ti+2
    const int tj   = t & 3;          // N rows 3*tj..3*tj+2
    const int bg0  = blockIdx.x * B_PER_BLK;

    // ---- staging address precompute (6 float4 per thread per chunk)
    const float* gsrc[NSTAGE];
    uint32_t     soff[NSTAGE];       // byte offset within one buffer
    const uint32_t smem_b0 = (uint32_t)__cvta_generic_to_shared(&tile[0][0]);
    #pragma unroll
    for (int s = 0; s < NSTAGE; ++s) {
        int f   = tid + THREADS * s;           // 0..767
        int sb  = f / (ROWS * 8);              // elem 0..3
        int rem = f - sb * (ROWS * 8);
        int row = rem >> 3;                    // 0..23
        int k4  = rem & 7;
        const float* base = (row < NV)
            ? SV_A + ((size_t)row        * BATCH + (bg0 + sb)) * DIM
            : SV_N + ((size_t)(row - NV) * BATCH + (bg0 + sb)) * DIM;
        gsrc[s] = base + k4 * 4;
        soff[s] = (uint32_t)((sb * BAREA + row * PITCH + k4 * 4) * 4);
    }

    // prologue: issue chunks 0 and 1
    #pragma unroll
    for (int s = 0; s < NSTAGE; ++s)
        cp_async16(smem_b0 + soff[s], gsrc[s]);
    CP_COMMIT();
    #pragma unroll
    for (int s = 0; s < NSTAGE; ++s)
        cp_async16(smem_b0 + (uint32_t)(TILEF * 4) + soff[s], gsrc[s] + CHUNK);
    CP_COMMIT();

    float G[3][3] = {{0.f,0.f,0.f},{0.f,0.f,0.f},{0.f,0.f,0.f}};
    float nacc = 0.f;

    #pragma unroll
    for (int c = 0; c < NCHUNK; ++c) {
        if (c < NCHUNK - 1) { CP_WAIT(1); } else { CP_WAIT(0); }
        __syncthreads();                       // chunk c resident in buf c&1
        const float* tb = tile[c & 1];

        // ---- norm partial: thread owns one of the 96 rows (full 32 dims)
        if (tid < B_PER_BLK * ROWS) {
            int sb = tid / ROWS, row = tid - sb * ROWS;
            const float* rb = &tb[sb * BAREA + row * PITCH];
            float s0 = 0.f;
            #pragma unroll
            for (int k4 = 0; k4 < 8; ++k4) {
                float4 v = *reinterpret_cast<const float4*>(rb + k4 * 4);
                s0 += dot4(v, v);
            }
            nacc += s0;
        }

        // ---- 3x3 register-tiled Gram over this lane's 16-dim half
        const float* A0 = &tb[w * BAREA + (3 * ti)      * PITCH + h * 16];
        const float* N0 = &tb[w * BAREA + (NV + 3 * tj) * PITCH + h * 16];
        #pragma unroll
        for (int k4 = 0; k4 < 4; ++k4) {
            float4 a0 = *reinterpret_cast<const float4*>(A0 + 0 * PITCH + k4 * 4);
            float4 a1 = *reinterpret_cast<const float4*>(A0 + 1 * PITCH + k4 * 4);
            float4 a2 = *reinterpret_cast<const float4*>(A0 + 2 * PITCH + k4 * 4);
            float4 n0 = *reinterpret_cast<const float4*>(N0 + 0 * PITCH + k4 * 4);
            float4 n1 = *reinterpret_cast<const float4*>(N0 + 1 * PITCH + k4 * 4);
            float4 n2 = *reinterpret_cast<const float4*>(N0 + 2 * PITCH + k4 * 4);
            G[0][0] += dot4(a0, n0); G[0][1] += dot4(a0, n1); G[0][2] += dot4(a0, n2);
            G[1][0] += dot4(a1, n0); G[1][1] += dot4(a1, n1); G[1][2] += dot4(a1, n2);
            G[2][0] += dot4(a2, n0); G[2][1] += dot4(a2, n1); G[2][2] += dot4(a2, n2);
        }

        // ---- refill this buffer with chunk c+2 (after all readers done)
        if (c + 2 < NCHUNK) {
            __syncthreads();
            uint32_t dst = smem_b0 + (uint32_t)((c & 1) * TILEF * 4);
            #pragma unroll
            for (int s = 0; s < NSTAGE; ++s)
                cp_async16(dst + soff[s], gsrc[s] + (c + 2) * CHUNK);
            CP_COMMIT();
        }
    }

    // publish full-dim norms
    if (tid < B_PER_BLK * ROWS) nrm[tid] = nacc;
    __syncthreads();

    // ---- combine k-halves of G (offset-16 butterfly; both halves get total)
    #pragma unroll
    for (int r = 0; r < 3; ++r)
        #pragma unroll
        for (int cc = 0; cc < 3; ++cc)
            G[r][cc] += __shfl_xor_sync(0xffffffffu, G[r][cc], 16);

    // ---- d = na + nn - 2G, argmin with flat-index tie-break (first min)
    float dmin = 3.4e38f;
    int   imin = 0;
    #pragma unroll
    for (int r = 0; r < 3; ++r) {
        float na = nrm[w * ROWS + 3 * ti + r];
        #pragma unroll
        for (int cc = 0; cc < 3; ++cc) {
            float nn = nrm[w * ROWS + NV + 3 * tj + cc];
            float d  = na + nn - 2.f * G[r][cc];
            int   fl = (3 * ti + r) * NV + (3 * tj + cc);
            if (d < dmin || (d == dmin && fl < imin)) { dmin = d; imin = fl; }
        }
    }
    #pragma unroll
    for (int o = 1; o < 16; o <<= 1) {     // halves hold identical data
        float od = __shfl_xor_sync(0xffffffffu, dmin, o);
        int   oi = __shfl_xor_sync(0xffffffffu, imin, o);
        if (od < dmin || (od == dmin && oi < imin)) { dmin = od; imin = oi; }
    }

    // ---- epilogue distances: 32 lanes, 1 float4 per lane per array
    const int confA = imin / NV;
    const int confN = imin - confA * NV;
    const int bg    = bg0 + w;

    float4 ma  = reinterpret_cast<const float4*>(MV_A + (size_t)bg * DIM)[lane];
    float4 mn_ = reinterpret_cast<const float4*>(MV_N + (size_t)bg * DIM)[lane];
    float4 fa  = reinterpret_cast<const float4*>(SV_A + ((size_t)confA * BATCH + bg) * DIM)[lane];
    float4 fn  = reinterpret_cast<const float4*>(SV_N + ((size_t)confN * BATCH + bg) * DIM)[lane];

    float smv = sqdiff4(ma, mn_);
    float sa  = sqdiff4(ma, fa);
    float sc  = sqdiff4(mn_, fn);
    #pragma unroll
    for (int o = 1; o < 32; o <<= 1) {
        smv += __shfl_xor_sync(0xffffffffu, smv, o);
        sa  += __shfl_xor_sync(0xffffffffu, sa,  o);
        sc  += __shfl_xor_sync(0xffffffffu, sc,  o);
    }

    if (lane == 0) {
        float mc       = fmaxf(dmin, 0.f);
        float mv_inter = sqrtf(smv);
        float a_cl     = sqrtf(sa);
        float c_in     = sqrtf(sc);
        float loss = LAMDA * (fmaxf(BETA - mc, 0.f) + fmaxf(BETA - mv_inter, 0.f))
                   + fmaxf(a_cl - ALPHA, 0.f) + fmaxf(c_in - ALPHA, 0.f);
        float sqmc = sqrtf(mc);
        r_loss[w] = loss;
        r_cnt[w]  = (loss != 0.f) ? 1.f : 0.f;
        r_mc[w]   = sqmc;
        r_ac[w]   = sqrtf(a_cl) + sqrtf(c_in);
        r_mn[w]   = sqmc;
    }
    __syncthreads();

    // ---- per-block partial (fixed order -> deterministic) + ticket
    if (tid == 0) {
        float sl = 0.f, sn = 0.f, sm = 0.f, sa2 = 0.f, mn = 3.4e38f;
        #pragma unroll
        for (int i = 0; i < B_PER_BLK; ++i) {
            sl  += r_loss[i];
            sn  += r_cnt[i];
            sm  += r_mc[i];
            sa2 += r_ac[i];
            mn   = fminf(mn, r_mn[i]);
        }
        g_pl[blockIdx.x]   = sl;
        g_pc[blockIdx.x]   = sn;
        g_pm[blockIdx.x]   = sm;
        g_pa[blockIdx.x]   = sa2;
        g_pmin[blockIdx.x] = mn;
        __threadfence();
        unsigned int prev = atomicAdd(&g_ticket, 1u);
        s_islast = (prev == NBLOCKS - 1) ? 1 : 0;
    }
    __syncthreads();

    // ---- last block: deterministic final reduction over 1024 partials
    if (s_islast) {
        __threadfence();
        float al = 0.f, ac = 0.f, am = 0.f, aa = 0.f, amn = 3.4e38f;
        #pragma unroll
        for (int q = 0; q < NBLOCKS / THREADS; ++q) {   // 8, fixed order
            int i = tid + q * THREADS;
            al += g_pl[i];
            ac += g_pc[i];
            am += g_pm[i];
            aa += g_pa[i];
            amn = fminf(amn, g_pmin[i]);
        }
        red[0][tid] = al; red[1][tid] = ac; red[2][tid] = am;
        red[3][tid] = aa; red[4][tid] = amn;
        __syncthreads();
        for (int o = THREADS / 2; o > 0; o >>= 1) {
            if (tid < o) {
                red[0][tid] += red[0][tid + o];
                red[1][tid] += red[1][tid + o];
                red[2][tid] += red[2][tid + o];
                red[3][tid] += red[3][tid + o];
                red[4][tid]  = fminf(red[4][tid], red[4][tid + o]);
            }
            __syncthreads();
        }
        if (tid == 0) {
            const float inv = 1.f / (float)BATCH;
            if (out_size > 0) out[0] = red[0][0] * inv;          // avg_loss
            if (out_size > 1) out[1] = red[1][0];                // count_nonzero
            if (out_size > 2) out[2] = red[2][0] * inv;          // mean(sqrt(mc))
            if (out_size > 3) out[3] = 0.5f * red[3][0] * inv;   // cluster means
            if (out_size > 4) out[4] = red[4][0];                // min(sqrt(mc))
            for (int i = 5; i < out_size; ++i) out[i] = 0.f;
            g_ticket = 0;      // reset for next graph replay
        }
    }
}

extern "C" void kernel_launch(void* const* d_in, const int* in_sizes, int n_in,
                              void* d_out, int out_size)
{
    const float* SV_A = (const float*)d_in[0];
    const float* SV_N = (const float*)d_in[1];
    const float* MV_A = (const float*)d_in[2];
    const float* MV_N = (const float*)d_in[3];
    (void)in_sizes; (void)n_in;

    pil_fused<<<NBLOCKS, THREADS>>>(SV_A, SV_N, MV_A, MV_N,
                                    (float*)d_out, out_size);
}